// round 3
// baseline (speedup 1.0000x reference)
#include <cuda_runtime.h>
#include <math.h>

// Problem constants
#define NB    16
#define CC    512
#define HH    64
#define WW    96
#define HWP   (HH*WW)          // 6144 pixels per image
#define OREAL 54               // 36 loc + 18 score
#define OPAD  56               // padded outputs (mult of 8)
#define KC    32               // channels per k-chunk
#define TP    128              // pixels per block
#define NTHREADS 224           // 7 warps: 32 pixel-groups x 7 out-groups

// Output concatenation layout (floats): [rpn_loc | rpn_score | rpn_fg | anchor]
#define LOC_BASE  0
#define SC_BASE   3538944      // 16*6144*36
#define FG_BASE   5308416      // + 16*6144*18
#define ANCH_BASE 6193152      // + 16*6144*9   (anchors: 55296*4)

__device__ float g_Wt[CC * OPAD];   // W transposed: [c][o], zero-padded o>=54
__device__ float g_bias[OPAD];

#define FMA2(d, a, b) asm("fma.rn.f32x2 %0, %1, %2, %0;" : "+l"(d) : "l"(a), "l"(b))

// ---------------------------------------------------------------------------
// Pack loc_w (36,512) + score_w (18,512) into g_Wt[c][o] (c-major, padded)
// ---------------------------------------------------------------------------
__global__ void pack_w_kernel(const float* __restrict__ loc_w,
                              const float* __restrict__ loc_b,
                              const float* __restrict__ score_w,
                              const float* __restrict__ score_b) {
    int i = blockIdx.x * blockDim.x + threadIdx.x;
    if (i < CC * OPAD) {
        int c = i / OPAD, o = i % OPAD;
        float v = 0.0f;
        if (o < 36)       v = loc_w[o * CC + c];
        else if (o < 54)  v = score_w[(o - 36) * CC + c];
        g_Wt[c * OPAD + o] = v;
    }
    if (i < OPAD) {
        float b = 0.0f;
        if (i < 36)       b = loc_b[i];
        else if (i < 54)  b = score_b[i - 36];
        g_bias[i] = b;
    }
}

// ---------------------------------------------------------------------------
// Anchors: input-independent. Double math then f32 cast matches numpy ref.
// ---------------------------------------------------------------------------
__global__ void anchor_kernel(float* __restrict__ out_anch) {
    int idx = blockIdx.x * blockDim.x + threadIdx.x;  // one anchor per thread
    if (idx >= HWP * 9) return;
    int hw = idx / 9, a = idx % 9;
    int hy = hw / WW, wx = hw % WW;

    const double ratios[3] = {0.5, 1.0, 2.0};
    const double scales[3] = {8.0, 16.0, 32.0};
    double r = ratios[a / 3];
    double s = scales[a % 3];
    double ha = 16.0 * s * sqrt(r);
    double wa = 16.0 * s * sqrt(1.0 / r);

    float sy = (float)(hy * 16);
    float sx = (float)(wx * 16);
    float4 v;
    v.x = sy + (float)(8.0 - ha * 0.5);
    v.y = sx + (float)(8.0 - wa * 0.5);
    v.z = sy + (float)(8.0 + ha * 0.5);
    v.w = sx + (float)(8.0 + wa * 0.5);
    reinterpret_cast<float4*>(out_anch)[idx] = v;
}

// ---------------------------------------------------------------------------
// Main: skinny GEMM (C=512 contraction -> 56 outputs) + bias + softmax pair
// Block: 128 pixels x 56 outs. Thread: 4 px x 8 outs via 16 f32x2 accum.
// ---------------------------------------------------------------------------
__global__ __launch_bounds__(NTHREADS)
void rpn_main_kernel(const float* __restrict__ x, float* __restrict__ out) {
    __shared__ __align__(16) float  xs[KC][TP];     // 16 KB
    __shared__ __align__(16) float2 ws[KC][OPAD];   // 14 KB, lane-duplicated W

    const int tid = threadIdx.x;
    const int pg  = tid & 31;    // pixel group: pixels pg*4 .. pg*4+3
    const int og  = tid >> 5;    // out group:   outs  og*8 .. og*8+7
    const int hw0 = blockIdx.x * TP;
    const int n   = blockIdx.y;

    const float* xn = x + (size_t)n * CC * HWP + hw0;

    unsigned long long acc[2][8];   // [pixel-pair][out], f32x2 packed, init 0
    #pragma unroll
    for (int j = 0; j < 2; j++)
        #pragma unroll
        for (int o = 0; o < 8; o++) acc[j][o] = 0ull;

    // W staging index decomposition hoisted out of the k-loop (no div/mod in loop)
    const int wc0 = tid / OPAD;          // 0..3
    const int wo0 = tid - wc0 * OPAD;    // 0..55

    for (int k0 = 0; k0 < CC; k0 += KC) {
        // Stage x tile: KC x TP floats = 1024 float4, coalesced along HW
        for (int i = tid; i < (KC * TP) / 4; i += NTHREADS) {
            int c  = i >> 5;       // 32 float4 per 128-float row
            int p4 = i & 31;
            float4 v = *reinterpret_cast<const float4*>(
                xn + (size_t)(k0 + c) * HWP + p4 * 4);
            *reinterpret_cast<float4*>(&xs[c][p4 * 4]) = v;
        }
        // Stage W chunk (KC*OPAD = 1792 = 8*NTHREADS), duplicated into f32x2 lanes
        #pragma unroll
        for (int r = 0; r < 8; r++) {
            int c = wc0 + r * 4;         // NTHREADS/OPAD = 4 rows per pass
            float v = g_Wt[(k0 + c) * OPAD + wo0];
            ws[c][wo0] = make_float2(v, v);
        }
        __syncthreads();

        #pragma unroll
        for (int c = 0; c < KC; c++) {
            ulonglong2 xv = *reinterpret_cast<const ulonglong2*>(&xs[c][pg * 4]);
            const ulonglong2* wp =
                reinterpret_cast<const ulonglong2*>(&ws[c][og * 8]);
            ulonglong2 w01 = wp[0], w23 = wp[1], w45 = wp[2], w67 = wp[3];

            FMA2(acc[0][0], xv.x, w01.x);  FMA2(acc[1][0], xv.y, w01.x);
            FMA2(acc[0][1], xv.x, w01.y);  FMA2(acc[1][1], xv.y, w01.y);
            FMA2(acc[0][2], xv.x, w23.x);  FMA2(acc[1][2], xv.y, w23.x);
            FMA2(acc[0][3], xv.x, w23.y);  FMA2(acc[1][3], xv.y, w23.y);
            FMA2(acc[0][4], xv.x, w45.x);  FMA2(acc[1][4], xv.y, w45.x);
            FMA2(acc[0][5], xv.x, w45.y);  FMA2(acc[1][5], xv.y, w45.y);
            FMA2(acc[0][6], xv.x, w67.x);  FMA2(acc[1][6], xv.y, w67.x);
            FMA2(acc[0][7], xv.x, w67.y);  FMA2(acc[1][7], xv.y, w67.y);
        }
        __syncthreads();
    }

    // Epilogue
    const int obase = og * 8;
    float bias[8];
    #pragma unroll
    for (int o = 0; o < 8; o++) bias[o] = g_bias[obase + o];

    #pragma unroll
    for (int j = 0; j < 2; j++) {
        #pragma unroll
        for (int h2 = 0; h2 < 2; h2++) {
            int p    = pg * 4 + j * 2 + h2;
            int gpix = n * HWP + hw0 + p;

            float vals[8];
            #pragma unroll
            for (int o = 0; o < 8; o++) {
                unsigned long long u = acc[j][o];
                unsigned int bits = h2 ? (unsigned int)(u >> 32)
                                       : (unsigned int)u;
                vals[o] = __uint_as_float(bits) + bias[o];
            }

            // raw loc / score outputs
            #pragma unroll
            for (int o = 0; o < 8; o++) {
                int oo = obase + o;
                if (oo < 36) {
                    out[LOC_BASE + (size_t)gpix * 36 + oo] = vals[o];
                } else if (oo < 54) {
                    out[SC_BASE + (size_t)gpix * 18 + (oo - 36)] = vals[o];
                }
            }
            // fg scores: softmax over (s[2a], s[2a+1]) picking class 1
            #pragma unroll
            for (int o = 0; o < 8; o += 2) {
                int oo = obase + o;
                if (oo >= 36 && oo + 1 < 54) {
                    int a = (oo - 36) >> 1;
                    float s0 = vals[o], s1 = vals[o + 1];
                    float fg = 1.0f / (1.0f + __expf(s0 - s1));
                    out[FG_BASE + (size_t)gpix * 9 + a] = fg;
                }
            }
        }
    }
}

// ---------------------------------------------------------------------------
extern "C" void kernel_launch(void* const* d_in, const int* in_sizes, int n_in,
                              void* d_out, int out_size) {
    (void)in_sizes; (void)n_in; (void)out_size;
    const float* x       = (const float*)d_in[0];
    const float* loc_w   = (const float*)d_in[1];
    const float* loc_b   = (const float*)d_in[2];
    const float* score_w = (const float*)d_in[3];
    const float* score_b = (const float*)d_in[4];
    float* out = (float*)d_out;

    pack_w_kernel<<<(CC * OPAD + 255) / 256, 256>>>(loc_w, loc_b, score_w, score_b);
    anchor_kernel<<<(HWP * 9 + 127) / 128, 128>>>(out + ANCH_BASE);

    dim3 grid(HWP / TP, NB);
    rpn_main_kernel<<<grid, NTHREADS>>>(x, out);
}

// round 5
// speedup vs baseline: 1.6526x; 1.6526x over previous
#include <cuda_runtime.h>
#include <cuda_bf16.h>
#include <math.h>
#include <stdint.h>

// ---------------------------------------------------------------- constants
#define NB     16
#define CC     512
#define HH     64
#define WW     96
#define HWP    6144            // 64*96
#define PX_TILE 128            // pixels per CTA
#define TILES_PER_IMG 48       // 6144/128
#define KC     64              // channels per K-chunk
#define NCHUNK 8               // 512/64
#define NTILES 7               // 7 n-tiles of 8 = 56 cols (54 real)

// Output layout (floats): [rpn_loc | rpn_score | rpn_fg | anchor]
#define LOC_BASE  0
#define SC_BASE   3538944
#define FG_BASE   5308416
#define ANCH_BASE 6193152

// B fragments: [pass(2)][chunk(8)][ktile(4)][lane(32)][16 u32 (7 ntiles*2 + pad)]
__device__ uint32_t g_bfrag[2 * NCHUNK * 4 * 32 * 16];   // 128 KB
__device__ float g_bias[64];

// ---------------------------------------------------------------- helpers
__device__ __forceinline__ uint32_t smem_u32(const void* p) {
    uint32_t a;
    asm("{ .reg .u64 t; cvta.to.shared.u64 t, %1; cvt.u32.u64 %0, t; }"
        : "=r"(a) : "l"(p));
    return a;
}

#define LDSM4(r, addr)                                                        \
    asm volatile("ldmatrix.sync.aligned.m8n8.x4.shared.b16 {%0,%1,%2,%3}, [%4];" \
        : "=r"((r)[0]), "=r"((r)[1]), "=r"((r)[2]), "=r"((r)[3])              \
        : "r"(addr))

#define MMA16816(c, a, b0, b1)                                                \
    asm volatile("mma.sync.aligned.m16n8k16.row.col.f32.bf16.bf16.f32 "       \
        "{%0,%1,%2,%3}, {%4,%5,%6,%7}, {%8,%9}, {%0,%1,%2,%3};"               \
        : "+f"((c)[0]), "+f"((c)[1]), "+f"((c)[2]), "+f"((c)[3])              \
        : "r"((a)[0]), "r"((a)[1]), "r"((a)[2]), "r"((a)[3]),                 \
          "r"(b0), "r"(b1))

__device__ __forceinline__ uint32_t sw128(uint32_t off) {
    return off ^ ((off >> 3) & 0x70);
}

// ---------------------------------------------------------------- pack W
// Bake per-lane mma.sync B fragments (bf16 hi/lo split) + bias.
__global__ void pack_w_kernel(const float* __restrict__ loc_w,
                              const float* __restrict__ loc_b,
                              const float* __restrict__ score_w,
                              const float* __restrict__ score_b) {
    int i = blockIdx.x * blockDim.x + threadIdx.x;   // 2*8*4*32*8 = 16384
    if (i < 16384) {
        int p    = i >> 13;          // 0 hi, 1 lo
        int j    = (i >> 10) & 7;    // chunk
        int kt   = (i >> 8) & 3;     // ktile
        int lane = (i >> 3) & 31;
        int nts  = i & 7;            // ntile slot (7 = pad)
        int o    = nts * 8 + (lane >> 2);
        int k0   = j * KC + kt * 16 + 2 * (lane & 3);

        float w[4];
        #pragma unroll
        for (int q = 0; q < 4; q++) {
            int c = k0 + (q & 1) + (q >> 1) * 8;
            float v = 0.0f;
            if (o < 36)       v = loc_w[o * CC + c];
            else if (o < 54)  v = score_w[(o - 36) * CC + c];
            w[q] = v;
        }
        unsigned short u[4];
        #pragma unroll
        for (int q = 0; q < 4; q++) {
            __nv_bfloat16 hb = __float2bfloat16_rn(w[q]);
            if (p == 0) u[q] = __bfloat16_as_ushort(hb);
            else        u[q] = __bfloat16_as_ushort(
                                   __float2bfloat16_rn(w[q] - __bfloat162float(hb)));
        }
        uint32_t b0 = (uint32_t)u[0] | ((uint32_t)u[1] << 16);
        uint32_t b1 = (uint32_t)u[2] | ((uint32_t)u[3] << 16);
        int frag = ((p * NCHUNK + j) * 4 + kt) * 32 + lane;
        if (nts < 8) {
            g_bfrag[frag * 16 + nts * 2]     = b0;
            g_bfrag[frag * 16 + nts * 2 + 1] = b1;
        }
    }
    if (i < 64) {
        float b = 0.0f;
        if (i < 36)       b = loc_b[i];
        else if (i < 54)  b = score_b[i - 36];
        g_bias[i] = b;
    }
}

// ---------------------------------------------------------------- anchors
__global__ void anchor_kernel(float* __restrict__ out_anch) {
    int idx = blockIdx.x * blockDim.x + threadIdx.x;
    if (idx >= HWP * 9) return;
    int hw = idx / 9, a = idx % 9;
    int hy = hw / WW, wx = hw % WW;
    const double ratios[3] = {0.5, 1.0, 2.0};
    const double scales[3] = {8.0, 16.0, 32.0};
    double r = ratios[a / 3];
    double s = scales[a % 3];
    double ha = 16.0 * s * sqrt(r);
    double wa = 16.0 * s * sqrt(1.0 / r);
    float sy = (float)(hy * 16);
    float sx = (float)(wx * 16);
    float4 v;
    v.x = sy + (float)(8.0 - ha * 0.5);
    v.y = sx + (float)(8.0 - wa * 0.5);
    v.z = sy + (float)(8.0 + ha * 0.5);
    v.w = sx + (float)(8.0 + wa * 0.5);
    reinterpret_cast<float4*>(out_anch)[idx] = v;
}

// ---------------------------------------------------------------- main
// CTA = 128 px x 56 outs, 4 warps (warp -> 32 px). HMMA m16n8k16 bf16,
// fp32 accum, 3-way hi/lo split summed into one accumulator set.
__global__ __launch_bounds__(128, 3)
void rpn_hmma_kernel(const float* __restrict__ x, float* __restrict__ out) {
    __shared__ __align__(1024) unsigned char xsh[PX_TILE * 128];  // 16 KB hi
    __shared__ __align__(1024) unsigned char xsl[PX_TILE * 128];  // 16 KB lo

    const int tid  = threadIdx.x;         // staging: thread = pixel
    const int lane = tid & 31;
    const int wid  = tid >> 5;
    const int b    = blockIdx.x;
    const int n    = b / TILES_PER_IMG;
    const int px0  = (b % TILES_PER_IMG) * PX_TILE;

    const uint32_t xsh_u = smem_u32(xsh);
    const uint32_t xsl_u = smem_u32(xsl);

    float acc[2][NTILES][4];
    #pragma unroll
    for (int mt = 0; mt < 2; mt++)
        #pragma unroll
        for (int nt = 0; nt < NTILES; nt++)
            #pragma unroll
            for (int q = 0; q < 4; q++) acc[mt][nt][q] = 0.0f;

    const float* xp = x + (size_t)n * CC * HWP + px0 + tid;

    // ldmatrix lane address components (constant across chunks)
    const uint32_t arow = (uint32_t)(lane & 15);
    const uint32_t aseg = (uint32_t)(((lane >> 4) & 1) * 16);
    const int pbase = wid * 32;

    for (int j = 0; j < NCHUNK; j++) {
        __syncthreads();
        // ---- stage x chunk: fp32 -> bf16 hi/lo -> swizzled SMEM
        const float* xc = xp + (size_t)(j * KC) * HWP;
        #pragma unroll 8
        for (int k0 = 0; k0 < KC; k0 += 2) {
            float f0 = xc[(size_t)k0 * HWP];
            float f1 = xc[(size_t)(k0 + 1) * HWP];
            uint32_t h;   // {hi16=bf16(f1), lo16=bf16(f0)}
            asm("cvt.rn.bf16x2.f32 %0, %1, %2;" : "=r"(h) : "f"(f1), "f"(f0));
            float h0 = __uint_as_float(h << 16);
            float h1 = __uint_as_float(h & 0xFFFF0000u);
            float r0 = f0 - h0, r1 = f1 - h1;
            uint32_t l;
            asm("cvt.rn.bf16x2.f32 %0, %1, %2;" : "=r"(l) : "f"(r1), "f"(r0));
            uint32_t sw = sw128((uint32_t)(tid * 128 + k0 * 2));
            *reinterpret_cast<uint32_t*>(xsh + sw) = h;
            *reinterpret_cast<uint32_t*>(xsl + sw) = l;
        }
        __syncthreads();

        // ---- compute: 4 ktiles x (2 mt x 7 nt x 3 passes) HMMA
        #pragma unroll
        for (int kt = 0; kt < 4; kt++) {
            uint32_t ah[2][4], al[2][4];
            #pragma unroll
            for (int mt = 0; mt < 2; mt++) {
                uint32_t off = (uint32_t)((pbase + mt * 16 + arow) * 128)
                             + (uint32_t)(kt * 32) + aseg;
                uint32_t sw = sw128(off);
                LDSM4(ah[mt], xsh_u + sw);
                LDSM4(al[mt], xsl_u + sw);
            }
            const uint4* bh4 = reinterpret_cast<const uint4*>(
                g_bfrag + (size_t)(((0 * NCHUNK + j) * 4 + kt) * 32 + lane) * 16);
            const uint4* bl4 = reinterpret_cast<const uint4*>(
                g_bfrag + (size_t)(((1 * NCHUNK + j) * 4 + kt) * 32 + lane) * 16);
            uint4 hq0 = bh4[0], hq1 = bh4[1], hq2 = bh4[2], hq3 = bh4[3];
            uint4 lq0 = bl4[0], lq1 = bl4[1], lq2 = bl4[2], lq3 = bl4[3];
            uint32_t bh[14] = {hq0.x, hq0.y, hq0.z, hq0.w, hq1.x, hq1.y, hq1.z,
                               hq1.w, hq2.x, hq2.y, hq2.z, hq2.w, hq3.x, hq3.y};
            uint32_t bl[14] = {lq0.x, lq0.y, lq0.z, lq0.w, lq1.x, lq1.y, lq1.z,
                               lq1.w, lq2.x, lq2.y, lq2.z, lq2.w, lq3.x, lq3.y};

            #pragma unroll
            for (int nt = 0; nt < NTILES; nt++) {
                MMA16816(acc[0][nt], ah[0], bh[2 * nt], bh[2 * nt + 1]);
                MMA16816(acc[1][nt], ah[1], bh[2 * nt], bh[2 * nt + 1]);
                MMA16816(acc[0][nt], ah[0], bl[2 * nt], bl[2 * nt + 1]);
                MMA16816(acc[1][nt], ah[1], bl[2 * nt], bl[2 * nt + 1]);
                MMA16816(acc[0][nt], al[0], bh[2 * nt], bh[2 * nt + 1]);
                MMA16816(acc[1][nt], al[1], bh[2 * nt], bh[2 * nt + 1]);
            }
        }
    }

    // ---- epilogue straight from fragments
    const int l4 = lane >> 2;
    const int l2 = (lane & 3) * 2;
    float bias0[NTILES], bias1[NTILES];
    #pragma unroll
    for (int nt = 0; nt < NTILES; nt++) {
        bias0[nt] = g_bias[nt * 8 + l2];
        bias1[nt] = g_bias[nt * 8 + l2 + 1];
    }

    #pragma unroll
    for (int mt = 0; mt < 2; mt++) {
        #pragma unroll
        for (int h = 0; h < 2; h++) {
            int pix = wid * 32 + mt * 16 + h * 8 + l4;
            size_t gpix = (size_t)n * HWP + px0 + pix;
            float* lb = out + gpix * 36;
            float* sb = out + SC_BASE + gpix * 18;
            float* fb = out + FG_BASE + gpix * 9;
            #pragma unroll
            for (int nt = 0; nt < NTILES; nt++) {
                int col = nt * 8 + l2;
                float v0 = acc[mt][nt][2 * h]     + bias0[nt];
                float v1 = acc[mt][nt][2 * h + 1] + bias1[nt];
                if (col < 36) {
                    *reinterpret_cast<float2*>(lb + col) = make_float2(v0, v1);
                } else if (col < 54) {
                    *reinterpret_cast<float2*>(sb + (col - 36)) = make_float2(v0, v1);
                    fb[(col - 36) >> 1] = 1.0f / (1.0f + __expf(v0 - v1));
                }
            }
        }
    }
}

// ---------------------------------------------------------------- launch
extern "C" void kernel_launch(void* const* d_in, const int* in_sizes, int n_in,
                              void* d_out, int out_size) {
    (void)in_sizes; (void)n_in; (void)out_size;
    const float* x       = (const float*)d_in[0];
    const float* loc_w   = (const float*)d_in[1];
    const float* loc_b   = (const float*)d_in[2];
    const float* score_w = (const float*)d_in[3];
    const float* score_b = (const float*)d_in[4];
    float* out = (float*)d_out;

    pack_w_kernel<<<(16384 + 255) / 256, 256>>>(loc_w, loc_b, score_w, score_b);
    anchor_kernel<<<(HWP * 9 + 127) / 128, 128>>>(out + ANCH_BASE);

    rpn_hmma_kernel<<<NB * TILES_PER_IMG, 128>>>(x, out);
}

// round 6
// speedup vs baseline: 2.3908x; 1.4466x over previous
#include <cuda_runtime.h>
#include <cuda_fp16.h>
#include <math.h>
#include <stdint.h>

// ---------------------------------------------------------------- constants
#define NB     16
#define CC     512
#define HH     64
#define WW     96
#define HWP    6144            // 64*96
#define PX_TILE 128            // pixels per CTA
#define TILES_PER_IMG 48       // 6144/128
#define KC     64              // channels per K-chunk
#define NCHUNK 8               // 512/64
#define NTILES 7               // 7 n-tiles of 8 = 56 cols (54 real)

// Output layout (floats): [rpn_loc | rpn_score | rpn_fg | anchor]
#define LOC_BASE  0
#define SC_BASE   3538944
#define FG_BASE   5308416
#define ANCH_BASE 6193152

// B fragments (fp16, single pass): [chunk(8)][ktile(4)][lane(32)][16 u32]
__device__ uint32_t g_bfrag[NCHUNK * 4 * 32 * 16];   // 64 KB
__device__ float g_bias[64];

// ---------------------------------------------------------------- helpers
__device__ __forceinline__ uint32_t smem_u32(const void* p) {
    uint32_t a;
    asm("{ .reg .u64 t; cvta.to.shared.u64 t, %1; cvt.u32.u64 %0, t; }"
        : "=r"(a) : "l"(p));
    return a;
}

#define LDSM4(r, addr)                                                        \
    asm volatile("ldmatrix.sync.aligned.m8n8.x4.shared.b16 {%0,%1,%2,%3}, [%4];" \
        : "=r"((r)[0]), "=r"((r)[1]), "=r"((r)[2]), "=r"((r)[3])              \
        : "r"(addr))

#define MMA16816(c, a, b0, b1)                                                \
    asm volatile("mma.sync.aligned.m16n8k16.row.col.f32.f16.f16.f32 "         \
        "{%0,%1,%2,%3}, {%4,%5,%6,%7}, {%8,%9}, {%0,%1,%2,%3};"               \
        : "+f"((c)[0]), "+f"((c)[1]), "+f"((c)[2]), "+f"((c)[3])              \
        : "r"((a)[0]), "r"((a)[1]), "r"((a)[2]), "r"((a)[3]),                 \
          "r"(b0), "r"(b1))

__device__ __forceinline__ uint32_t sw128(uint32_t off) {
    return off ^ ((off >> 3) & 0x70);
}

// ---------------------------------------------------------------- helper kernel
// Fused: B-fragment bake (fp16) + bias + anchors. 2 launches/call total so
// the ncu capture slot lands on the main kernel.
__global__ void pack_w_kernel(const float* __restrict__ loc_w,
                              const float* __restrict__ loc_b,
                              const float* __restrict__ score_w,
                              const float* __restrict__ score_b,
                              float* __restrict__ out_anch) {
    int i = blockIdx.x * blockDim.x + threadIdx.x;

    // ---- B fragments: 8*4*32*8 = 8192 slots
    if (i < 8192) {
        int j    = i >> 10;          // chunk
        int kt   = (i >> 8) & 3;     // ktile
        int lane = (i >> 3) & 31;
        int nts  = i & 7;            // ntile slot (7 = zero pad)
        int o    = nts * 8 + (lane >> 2);
        int k0   = j * KC + kt * 16 + 2 * (lane & 3);

        float w[4];
        #pragma unroll
        for (int q = 0; q < 4; q++) {
            int c = k0 + (q & 1) + (q >> 1) * 8;
            float v = 0.0f;
            if (o < 36)       v = loc_w[o * CC + c];
            else if (o < 54)  v = score_w[(o - 36) * CC + c];
            w[q] = v;
        }
        unsigned short u[4];
        #pragma unroll
        for (int q = 0; q < 4; q++)
            u[q] = __half_as_ushort(__float2half_rn(w[q]));
        int frag = (j * 4 + kt) * 32 + lane;
        g_bfrag[frag * 16 + nts * 2]     = (uint32_t)u[0] | ((uint32_t)u[1] << 16);
        g_bfrag[frag * 16 + nts * 2 + 1] = (uint32_t)u[2] | ((uint32_t)u[3] << 16);
    }

    // ---- bias
    if (i < 64) {
        float b = 0.0f;
        if (i < 36)       b = loc_b[i];
        else if (i < 54)  b = score_b[i - 36];
        g_bias[i] = b;
    }

    // ---- anchors
    if (i < HWP * 9) {
        int hw = i / 9, a = i % 9;
        int hy = hw / WW, wx = hw % WW;
        const double ratios[3] = {0.5, 1.0, 2.0};
        const double scales[3] = {8.0, 16.0, 32.0};
        double r = ratios[a / 3];
        double s = scales[a % 3];
        double ha = 16.0 * s * sqrt(r);
        double wa = 16.0 * s * sqrt(1.0 / r);
        float sy = (float)(hy * 16);
        float sx = (float)(wx * 16);
        float4 v;
        v.x = sy + (float)(8.0 - ha * 0.5);
        v.y = sx + (float)(8.0 - wa * 0.5);
        v.z = sy + (float)(8.0 + ha * 0.5);
        v.w = sx + (float)(8.0 + wa * 0.5);
        reinterpret_cast<float4*>(out_anch)[i] = v;
    }
}

// ---------------------------------------------------------------- main
// CTA = 128 px x 56 outs, 4 warps. HMMA m16n8k16 fp16 single pass, fp32 accum.
// Double-buffered SMEM staging: stage chunk j+1 interleaved with compute j.
__global__ __launch_bounds__(128, 4)
void rpn_hmma_kernel(const float* __restrict__ x, float* __restrict__ out) {
    __shared__ __align__(1024) unsigned char xs[2][PX_TILE * 128];  // 2 x 16 KB

    const int tid  = threadIdx.x;         // staging: thread = pixel
    const int lane = tid & 31;
    const int wid  = tid >> 5;
    const int b    = blockIdx.x;
    const int n    = b / TILES_PER_IMG;
    const int px0  = (b % TILES_PER_IMG) * PX_TILE;

    const uint32_t xs_u = smem_u32(xs);

    float acc[2][NTILES][4];
    #pragma unroll
    for (int mt = 0; mt < 2; mt++)
        #pragma unroll
        for (int nt = 0; nt < NTILES; nt++)
            #pragma unroll
            for (int q = 0; q < 4; q++) acc[mt][nt][q] = 0.0f;

    const float* xp = x + (size_t)n * CC * HWP + px0 + tid;

    const uint32_t arow = (uint32_t)(lane & 15);
    const uint32_t aseg = (uint32_t)(((lane >> 4) & 1) * 16);
    const int pbase = wid * 32;

    // ---- staging macro: chunk j -> buffer buf (fp32 -> fp16, SW128)
    #define STAGE(J, BUF) do {                                                 \
        const float* xc = xp + (size_t)((J) * KC) * HWP;                       \
        unsigned char* dst = xs[(BUF)];                                        \
        _Pragma("unroll")                                                      \
        for (int k0 = 0; k0 < KC; k0 += 8) {                                   \
            float f[8];                                                        \
            _Pragma("unroll")                                                  \
            for (int t = 0; t < 8; t++) f[t] = xc[(size_t)(k0 + t) * HWP];     \
            uint32_t r[4];                                                     \
            _Pragma("unroll")                                                  \
            for (int t = 0; t < 4; t++)                                        \
                asm("cvt.rn.f16x2.f32 %0, %1, %2;"                             \
                    : "=r"(r[t]) : "f"(f[2 * t + 1]), "f"(f[2 * t]));          \
            *reinterpret_cast<uint4*>(dst + sw128((uint32_t)(tid * 128 + k0 * 2))) \
                = make_uint4(r[0], r[1], r[2], r[3]);                          \
        }                                                                      \
    } while (0)

    STAGE(0, 0);
    __syncthreads();

    for (int j = 0; j < NCHUNK; j++) {
        // prefetch next chunk into the other buffer (overlaps with MMAs below)
        if (j + 1 < NCHUNK) STAGE(j + 1, (j + 1) & 1);

        const uint32_t bufbase = xs_u + (uint32_t)((j & 1) * (PX_TILE * 128));
        #pragma unroll
        for (int kt = 0; kt < 4; kt++) {
            uint32_t ah[2][4];
            #pragma unroll
            for (int mt = 0; mt < 2; mt++) {
                uint32_t off = (uint32_t)((pbase + mt * 16 + arow) * 128)
                             + (uint32_t)(kt * 32) + aseg;
                LDSM4(ah[mt], bufbase + sw128(off));
            }
            const uint4* b4 = reinterpret_cast<const uint4*>(
                g_bfrag + (size_t)((j * 4 + kt) * 32 + lane) * 16);
            uint4 q0 = b4[0], q1 = b4[1], q2 = b4[2], q3 = b4[3];
            uint32_t bh[14] = {q0.x, q0.y, q0.z, q0.w, q1.x, q1.y, q1.z,
                               q1.w, q2.x, q2.y, q2.z, q2.w, q3.x, q3.y};

            #pragma unroll
            for (int nt = 0; nt < NTILES; nt++) {
                MMA16816(acc[0][nt], ah[0], bh[2 * nt], bh[2 * nt + 1]);
                MMA16816(acc[1][nt], ah[1], bh[2 * nt], bh[2 * nt + 1]);
            }
        }
        __syncthreads();
    }

    // ---- epilogue straight from fragments
    const int l4 = lane >> 2;
    const int l2 = (lane & 3) * 2;
    float bias0[NTILES], bias1[NTILES];
    #pragma unroll
    for (int nt = 0; nt < NTILES; nt++) {
        bias0[nt] = g_bias[nt * 8 + l2];
        bias1[nt] = g_bias[nt * 8 + l2 + 1];
    }

    #pragma unroll
    for (int mt = 0; mt < 2; mt++) {
        #pragma unroll
        for (int h = 0; h < 2; h++) {
            int pix = wid * 32 + mt * 16 + h * 8 + l4;
            size_t gpix = (size_t)n * HWP + px0 + pix;
            float* lb = out + gpix * 36;
            float* sb = out + SC_BASE + gpix * 18;
            float* fb = out + FG_BASE + gpix * 9;
            #pragma unroll
            for (int nt = 0; nt < NTILES; nt++) {
                int col = nt * 8 + l2;
                float v0 = acc[mt][nt][2 * h]     + bias0[nt];
                float v1 = acc[mt][nt][2 * h + 1] + bias1[nt];
                if (col < 36) {
                    *reinterpret_cast<float2*>(lb + col) = make_float2(v0, v1);
                } else if (col < 54) {
                    *reinterpret_cast<float2*>(sb + (col - 36)) = make_float2(v0, v1);
                    fb[(col - 36) >> 1] = 1.0f / (1.0f + __expf(v0 - v1));
                }
            }
        }
    }
}

// ---------------------------------------------------------------- launch
extern "C" void kernel_launch(void* const* d_in, const int* in_sizes, int n_in,
                              void* d_out, int out_size) {
    (void)in_sizes; (void)n_in; (void)out_size;
    const float* x       = (const float*)d_in[0];
    const float* loc_w   = (const float*)d_in[1];
    const float* loc_b   = (const float*)d_in[2];
    const float* score_w = (const float*)d_in[3];
    const float* score_b = (const float*)d_in[4];
    float* out = (float*)d_out;

    pack_w_kernel<<<(HWP * 9 + 255) / 256, 256>>>(
        loc_w, loc_b, score_w, score_b, out + ANCH_BASE);

    rpn_hmma_kernel<<<NB * TILES_PER_IMG, 128>>>(x, out);
}

// round 7
// speedup vs baseline: 2.5520x; 1.0674x over previous
#include <cuda_runtime.h>
#include <cuda_fp16.h>
#include <math.h>
#include <stdint.h>

// ---------------------------------------------------------------- constants
#define NB     16
#define CC     512
#define HH     64
#define WW     96
#define HWP    6144            // 64*96
#define PX_TILE 128            // pixels per CTA
#define TILES_PER_IMG 48       // 6144/128
#define NKT    32              // 32 k-tiles of 16 = K 512
#define NTILES 7               // 7 n-tiles of 8 = 56 cols (54 real)

// Output layout (floats): [rpn_loc | rpn_score | rpn_fg | anchor]
#define LOC_BASE  0
#define SC_BASE   3538944
#define FG_BASE   5308416
#define ANCH_BASE 6193152

// B fragments (fp16): [ktile(32)][lane(32)][16 u32 (7 ntiles*2 + pad)]
__device__ uint32_t g_bfrag[NKT * 32 * 16];   // 64 KB
__device__ float g_bias[64];

// ---------------------------------------------------------------- helpers
#define MMA16816(c, a, b0, b1)                                                \
    asm volatile("mma.sync.aligned.m16n8k16.row.col.f32.f16.f16.f32 "         \
        "{%0,%1,%2,%3}, {%4,%5,%6,%7}, {%8,%9}, {%0,%1,%2,%3};"               \
        : "+f"((c)[0]), "+f"((c)[1]), "+f"((c)[2]), "+f"((c)[3])              \
        : "r"((a)[0]), "r"((a)[1]), "r"((a)[2]), "r"((a)[3]),                 \
          "r"(b0), "r"(b1))

#define CVT2(d, flo, fhi)                                                     \
    asm("cvt.rn.f16x2.f32 %0, %1, %2;" : "=r"(d) : "f"(fhi), "f"(flo))

// ---------------------------------------------------------------- helper kernel
// Fused: B-fragment bake (fp16) + bias + anchors. 2 launches/call total.
__global__ void pack_w_kernel(const float* __restrict__ loc_w,
                              const float* __restrict__ loc_b,
                              const float* __restrict__ score_w,
                              const float* __restrict__ score_b,
                              float* __restrict__ out_anch) {
    int i = blockIdx.x * blockDim.x + threadIdx.x;

    // ---- B fragments: 32*32*8 = 8192 slots
    if (i < 8192) {
        int kt   = i >> 8;           // ktile 0..31
        int lane = (i >> 3) & 31;
        int nts  = i & 7;            // ntile slot (7 = zero pad)
        int o    = nts * 8 + (lane >> 2);
        int k0   = kt * 16 + 2 * (lane & 3);

        float w[4];
        #pragma unroll
        for (int q = 0; q < 4; q++) {
            int c = k0 + (q & 1) + (q >> 1) * 8;
            float v = 0.0f;
            if (o < 36)       v = loc_w[o * CC + c];
            else if (o < 54)  v = score_w[(o - 36) * CC + c];
            w[q] = v;
        }
        unsigned short u[4];
        #pragma unroll
        for (int q = 0; q < 4; q++)
            u[q] = __half_as_ushort(__float2half_rn(w[q]));
        int frag = kt * 32 + lane;
        g_bfrag[frag * 16 + nts * 2]     = (uint32_t)u[0] | ((uint32_t)u[1] << 16);
        g_bfrag[frag * 16 + nts * 2 + 1] = (uint32_t)u[2] | ((uint32_t)u[3] << 16);
    }

    // ---- bias
    if (i < 64) {
        float b = 0.0f;
        if (i < 36)       b = loc_b[i];
        else if (i < 54)  b = score_b[i - 36];
        g_bias[i] = b;
    }

    // ---- anchors
    if (i < HWP * 9) {
        int hw = i / 9, a = i % 9;
        int hy = hw / WW, wx = hw % WW;
        const double ratios[3] = {0.5, 1.0, 2.0};
        const double scales[3] = {8.0, 16.0, 32.0};
        double r = ratios[a / 3];
        double s = scales[a % 3];
        double ha = 16.0 * s * sqrt(r);
        double wa = 16.0 * s * sqrt(1.0 / r);
        float sy = (float)(hy * 16);
        float sx = (float)(wx * 16);
        float4 v;
        v.x = sy + (float)(8.0 - ha * 0.5);
        v.y = sx + (float)(8.0 - wa * 0.5);
        v.z = sy + (float)(8.0 + ha * 0.5);
        v.w = sx + (float)(8.0 + wa * 0.5);
        reinterpret_cast<float4*>(out_anch)[i] = v;
    }
}

// ---------------------------------------------------------------- main
// CTA = 128 px x 56 outs, 4 independent warps (warp -> 32 px, 2 m-tiles).
// A fragments loaded DIRECTLY from global (16 LDG.32 / thread / ktile, dense
// 32B sectors), cvt to fp16 in regs, no SMEM, no barriers, no ldmatrix.
// 1-ktile register prefetch keeps ~64 sectors in flight per warp.
__global__ __launch_bounds__(128, 4)
void rpn_hmma_kernel(const float* __restrict__ x, float* __restrict__ out) {
    const int tid  = threadIdx.x;
    const int lane = tid & 31;
    const int wid  = tid >> 5;
    const int b    = blockIdx.x;
    const int n    = b / TILES_PER_IMG;
    const int px0  = (b % TILES_PER_IMG) * PX_TILE;

    float acc[2][NTILES][4];
    #pragma unroll
    for (int mt = 0; mt < 2; mt++)
        #pragma unroll
        for (int nt = 0; nt < NTILES; nt++)
            #pragma unroll
            for (int q = 0; q < 4; q++) acc[mt][nt][q] = 0.0f;

    // base: this lane's pixel row (fragment row l>>2), this lane's channel pair
    const float* xw = x + (size_t)n * CC * HWP + px0 + wid * 32 + (lane >> 2);
    const int csub = (lane & 3) * 2;

    // f[buf][dci*4 + dpi]: dci -> dc {0,1,8,9}, dpi -> dpx {0,8,16,24}
    float f[2][16];

    // preload ktile 0
    {
        const float* p = xw + (size_t)csub * HWP;
        #pragma unroll
        for (int dci = 0; dci < 4; dci++) {
            int dc = (dci & 1) + (dci >> 1) * 8;
            #pragma unroll
            for (int dpi = 0; dpi < 4; dpi++)
                f[0][dci * 4 + dpi] = p[(size_t)dc * HWP + dpi * 8];
        }
    }

    #pragma unroll 2
    for (int kt = 0; kt < NKT; kt++) {
        const int cur = kt & 1, nxt = cur ^ 1;

        // prefetch next ktile (16 independent LDG.32, front-batched)
        if (kt < NKT - 1) {
            const float* p = xw + (size_t)((kt + 1) * 16 + csub) * HWP;
            #pragma unroll
            for (int dci = 0; dci < 4; dci++) {
                int dc = (dci & 1) + (dci >> 1) * 8;
                #pragma unroll
                for (int dpi = 0; dpi < 4; dpi++)
                    f[nxt][dci * 4 + dpi] = p[(size_t)dc * HWP + dpi * 8];
            }
        }

        // convert current ktile to A fragments
        uint32_t a[2][4];
        #pragma unroll
        for (int mt = 0; mt < 2; mt++) {
            CVT2(a[mt][0], f[cur][0 * 4 + mt * 2],     f[cur][1 * 4 + mt * 2]);
            CVT2(a[mt][1], f[cur][0 * 4 + mt * 2 + 1], f[cur][1 * 4 + mt * 2 + 1]);
            CVT2(a[mt][2], f[cur][2 * 4 + mt * 2],     f[cur][3 * 4 + mt * 2]);
            CVT2(a[mt][3], f[cur][2 * 4 + mt * 2 + 1], f[cur][3 * 4 + mt * 2 + 1]);
        }

        // B fragments from global (L1-resident; identical across CTAs)
        const uint4* bp = reinterpret_cast<const uint4*>(
            g_bfrag + (size_t)(kt * 32 + lane) * 16);
        uint4 q0 = bp[0], q1 = bp[1];
        MMA16816(acc[0][0], a[0], q0.x, q0.y);
        MMA16816(acc[1][0], a[1], q0.x, q0.y);
        MMA16816(acc[0][1], a[0], q0.z, q0.w);
        MMA16816(acc[1][1], a[1], q0.z, q0.w);
        MMA16816(acc[0][2], a[0], q1.x, q1.y);
        MMA16816(acc[1][2], a[1], q1.x, q1.y);
        MMA16816(acc[0][3], a[0], q1.z, q1.w);
        MMA16816(acc[1][3], a[1], q1.z, q1.w);
        uint4 q2 = bp[2], q3 = bp[3];
        MMA16816(acc[0][4], a[0], q2.x, q2.y);
        MMA16816(acc[1][4], a[1], q2.x, q2.y);
        MMA16816(acc[0][5], a[0], q2.z, q2.w);
        MMA16816(acc[1][5], a[1], q2.z, q2.w);
        MMA16816(acc[0][6], a[0], q3.x, q3.y);
        MMA16816(acc[1][6], a[1], q3.x, q3.y);
    }

    // ---- epilogue straight from fragments
    const int l4 = lane >> 2;
    const int l2 = (lane & 3) * 2;
    float bias0[NTILES], bias1[NTILES];
    #pragma unroll
    for (int nt = 0; nt < NTILES; nt++) {
        bias0[nt] = g_bias[nt * 8 + l2];
        bias1[nt] = g_bias[nt * 8 + l2 + 1];
    }

    #pragma unroll
    for (int mt = 0; mt < 2; mt++) {
        #pragma unroll
        for (int h = 0; h < 2; h++) {
            int pix = wid * 32 + mt * 16 + h * 8 + l4;
            size_t gpix = (size_t)n * HWP + px0 + pix;
            float* lb = out + gpix * 36;
            float* sb = out + SC_BASE + gpix * 18;
            float* fb = out + FG_BASE + gpix * 9;
            #pragma unroll
            for (int nt = 0; nt < NTILES; nt++) {
                int col = nt * 8 + l2;
                float v0 = acc[mt][nt][2 * h]     + bias0[nt];
                float v1 = acc[mt][nt][2 * h + 1] + bias1[nt];
                if (col < 36) {
                    *reinterpret_cast<float2*>(lb + col) = make_float2(v0, v1);
                } else if (col < 54) {
                    *reinterpret_cast<float2*>(sb + (col - 36)) = make_float2(v0, v1);
                    fb[(col - 36) >> 1] = 1.0f / (1.0f + __expf(v0 - v1));
                }
            }
        }
    }
}

// ---------------------------------------------------------------- launch
extern "C" void kernel_launch(void* const* d_in, const int* in_sizes, int n_in,
                              void* d_out, int out_size) {
    (void)in_sizes; (void)n_in; (void)out_size;
    const float* x       = (const float*)d_in[0];
    const float* loc_w   = (const float*)d_in[1];
    const float* loc_b   = (const float*)d_in[2];
    const float* score_w = (const float*)d_in[3];
    const float* score_b = (const float*)d_in[4];
    float* out = (float*)d_out;

    pack_w_kernel<<<(HWP * 9 + 255) / 256, 256>>>(
        loc_w, loc_b, score_w, score_b, out + ANCH_BASE);

    rpn_hmma_kernel<<<NB * TILES_PER_IMG, 128>>>(x, out);
}